// round 15
// baseline (speedup 1.0000x reference)
#include <cuda_runtime.h>

typedef unsigned long long u64;

#define DD 17
#define HH 8
#define OO 6
#define EE 4

// __constant__: GW1 + GW2 only (2 memcpy graph nodes)
#define C_GW1 0            // 1088
#define C_GW2 1088         // 2048
__constant__ __align__(16) float cw[3136];

// shared: expert weights (divergent) + small gating params
#define S_EW1 0            // 544
#define S_EB1 544          // 32
#define S_EW2 576          // 256
#define S_EB2 832          // 32
#define S_EW3 864          // 192
#define S_EB3 1056         // 24 -> pad 1088
#define S_GB1 1088         // 64
#define S_GB2 1152         // 32
#define S_GW3 1184         // 128
#define S_GB3 1312         // 4 -> pad 1328
#define S_TOT 1328

__device__ __forceinline__ u64 pk2(float lo, float hi) {
    u64 r; asm("mov.b64 %0, {%1,%2};" : "=l"(r) : "f"(lo), "f"(hi)); return r;
}
__device__ __forceinline__ u64 dup2(float v) { return pk2(v, v); }
__device__ __forceinline__ void upk2(u64 v, float& lo, float& hi) {
    asm("mov.b64 {%0,%1}, %2;" : "=f"(lo), "=f"(hi) : "l"(v));
}
__device__ __forceinline__ u64 ffma2(u64 a, u64 b, u64 c) {
    u64 d; asm("fma.rn.f32x2 %0, %1, %2, %3;" : "=l"(d) : "l"(a), "l"(b), "l"(c)); return d;
}

// selected-expert MLP (smem weights, divergent by sel; x from registers)
__device__ __forceinline__ void expert_eval(const float* __restrict__ s,
                                            const float xv[DD], int sel,
                                            u64& o0, u64& o1, u64& o2)
{
    u64 e1p[4];
    {
        const ulonglong2* bp = (const ulonglong2*)&s[S_EB1 + sel * HH];
        ulonglong2 v0 = bp[0], v1 = bp[1];
        e1p[0] = v0.x; e1p[1] = v0.y; e1p[2] = v1.x; e1p[3] = v1.y;
    }
#pragma unroll
    for (int i = 0; i < DD; i++) {
        const u64 xi2 = dup2(xv[i]);
        const ulonglong2* wp = (const ulonglong2*)&s[S_EW1 + (sel * DD + i) * HH];
        ulonglong2 w0 = wp[0], w1 = wp[1];
        e1p[0] = ffma2(xi2, w0.x, e1p[0]);
        e1p[1] = ffma2(xi2, w0.y, e1p[1]);
        e1p[2] = ffma2(xi2, w1.x, e1p[2]);
        e1p[3] = ffma2(xi2, w1.y, e1p[3]);
    }
    float e1[HH];
    upk2(e1p[0], e1[0], e1[1]); upk2(e1p[1], e1[2], e1[3]);
    upk2(e1p[2], e1[4], e1[5]); upk2(e1p[3], e1[6], e1[7]);
#pragma unroll
    for (int h = 0; h < HH; h++) e1[h] = fmaxf(e1[h], 0.0f);

    u64 e2p[4];
    {
        const ulonglong2* bp = (const ulonglong2*)&s[S_EB2 + sel * HH];
        ulonglong2 v0 = bp[0], v1 = bp[1];
        e2p[0] = v0.x; e2p[1] = v0.y; e2p[2] = v1.x; e2p[3] = v1.y;
    }
#pragma unroll
    for (int h = 0; h < HH; h++) {
        const u64 hd = dup2(e1[h]);
        const ulonglong2* wp = (const ulonglong2*)&s[S_EW2 + (sel * HH + h) * HH];
        ulonglong2 w0 = wp[0], w1 = wp[1];
        e2p[0] = ffma2(hd, w0.x, e2p[0]);
        e2p[1] = ffma2(hd, w0.y, e2p[1]);
        e2p[2] = ffma2(hd, w1.x, e2p[2]);
        e2p[3] = ffma2(hd, w1.y, e2p[3]);
    }
    float e2[HH];
    upk2(e2p[0], e2[0], e2[1]); upk2(e2p[1], e2[2], e2[3]);
    upk2(e2p[2], e2[4], e2[5]); upk2(e2p[3], e2[6], e2[7]);
#pragma unroll
    for (int k = 0; k < HH; k++) e2[k] = fmaxf(e2[k], 0.0f);

    {
        const u64* bp = (const u64*)&s[S_EB3 + sel * OO];
        o0 = bp[0]; o1 = bp[1]; o2 = bp[2];
    }
#pragma unroll
    for (int k = 0; k < HH; k++) {
        const u64 kd = dup2(e2[k]);
        const u64* wp = (const u64*)&s[S_EW3 + (sel * HH + k) * OO];
        o0 = ffma2(kd, wp[0], o0);
        o1 = ffma2(kd, wp[1], o1);
        o2 = ffma2(kd, wp[2], o2);
    }
}

__global__ __launch_bounds__(128, 2) void moe_kernel(
    const float* __restrict__ x,
    const float* __restrict__ eW1, const float* __restrict__ eb1,
    const float* __restrict__ eW2, const float* __restrict__ eb2,
    const float* __restrict__ eW3, const float* __restrict__ eb3,
    const float* __restrict__ gb1, const float* __restrict__ gb2,
    const float* __restrict__ gW3, const float* __restrict__ gb3,
    float* __restrict__ pred, float* __restrict__ glog, int Bt, int B)
{
    __shared__ __align__(16) float s[S_TOT];
    const int t = threadIdx.x;
    // expert weights -> smem
    for (int i = t; i < 544; i += 128) s[S_EW1 + i] = eW1[i];
    if (t < 32)  s[S_EB1 + t] = eb1[t];
    for (int i = t; i < 256; i += 128) s[S_EW2 + i] = eW2[i];
    if (t >= 32 && t < 64) s[S_EB2 + (t - 32)] = eb2[t - 32];
    for (int i = t; i < 192; i += 128) s[S_EW3 + i] = eW3[i];
    if (t >= 64 && t < 88) s[S_EB3 + (t - 64)] = eb3[t - 64];
    // small gating params -> smem
    if (t < 64)  s[S_GB1 + t] = gb1[t];
    if (t >= 64 && t < 96) s[S_GB2 + (t - 64)] = gb2[t - 64];
    s[S_GW3 + t] = gW3[t];
    if (t >= 96 && t < 100) s[S_GB3 + (t - 96)] = gb3[t - 96];
    __syncthreads();

    const int b0 = blockIdx.x * 128 + t;
    if (b0 >= Bt) return;                 // tail threads of last block
    const int b1 = b0 + Bt;               // always < 2*Bt <= B
    const int b2 = b0 + 2 * Bt;           // may exceed B by <=2 threads
    const bool v2 = (b2 < B);
    const int b2c = v2 ? b2 : (B - 1);    // clamped load index

    // x rows: direct per-thread global loads into registers (once)
    float xa[DD], xb[DD], xc[DD];
    {
        const float* ra = x + (size_t)b0 * DD;
        const float* rb = x + (size_t)b1 * DD;
        const float* rc = x + (size_t)b2c * DD;
#pragma unroll
        for (int i = 0; i < DD; i++) { xa[i] = ra[i]; xb[i] = rb[i]; xc[i] = rc[i]; }
    }

    // gating layer-2 accumulators for 3 samples (bias from smem broadcast)
    u64 A2[16], B2[16], C2[16];
    {
        const ulonglong2* bp = (const ulonglong2*)&s[S_GB2];
#pragma unroll
        for (int q = 0; q < 8; q++) {
            ulonglong2 v = bp[q];
            A2[2*q]   = v.x; B2[2*q]   = v.x; C2[2*q]   = v.x;
            A2[2*q+1] = v.y; B2[2*q+1] = v.y; C2[2*q+1] = v.y;
        }
    }

    // layer1 in 8-neuron chunks (GW1 const), fused into layer2 (GW2 const)
    // each weight load now feeds 3 samples
#pragma unroll
    for (int c = 0; c < 8; c++) {
        u64 A1[4], B1[4], C1[4];
        {
            const ulonglong2* bp = (const ulonglong2*)&s[S_GB1 + c * 8];
            ulonglong2 v0 = bp[0], v1 = bp[1];
            A1[0] = v0.x; A1[1] = v0.y; A1[2] = v1.x; A1[3] = v1.y;
            B1[0] = v0.x; B1[1] = v0.y; B1[2] = v1.x; B1[3] = v1.y;
            C1[0] = v0.x; C1[1] = v0.y; C1[2] = v1.x; C1[3] = v1.y;
        }
#pragma unroll
        for (int i = 0; i < DD; i++) {
            const u64 xad = dup2(xa[i]);
            const u64 xbd = dup2(xb[i]);
            const u64 xcd = dup2(xc[i]);
            const ulonglong2* wp = (const ulonglong2*)&cw[C_GW1 + i * 64 + c * 8];
            ulonglong2 w0 = wp[0], w1 = wp[1];
            A1[0] = ffma2(xad, w0.x, A1[0]);
            B1[0] = ffma2(xbd, w0.x, B1[0]);
            C1[0] = ffma2(xcd, w0.x, C1[0]);
            A1[1] = ffma2(xad, w0.y, A1[1]);
            B1[1] = ffma2(xbd, w0.y, B1[1]);
            C1[1] = ffma2(xcd, w0.y, C1[1]);
            A1[2] = ffma2(xad, w1.x, A1[2]);
            B1[2] = ffma2(xbd, w1.x, B1[2]);
            C1[2] = ffma2(xcd, w1.x, C1[2]);
            A1[3] = ffma2(xad, w1.y, A1[3]);
            B1[3] = ffma2(xbd, w1.y, B1[3]);
            C1[3] = ffma2(xcd, w1.y, C1[3]);
        }
        // relu + feed into layer 2 (GW2 const rows of 32)
#pragma unroll
        for (int p = 0; p < 4; p++) {
            float a0, a1, b0f, b1f, c0f, c1f;
            upk2(A1[p], a0, a1);
            upk2(B1[p], b0f, b1f);
            upk2(C1[p], c0f, c1f);
#pragma unroll
            for (int half = 0; half < 2; half++) {
                const u64 had = dup2(fmaxf(half ? a1 : a0, 0.0f));
                const u64 hbd = dup2(fmaxf(half ? b1f : b0f, 0.0f));
                const u64 hcd = dup2(fmaxf(half ? c1f : c0f, 0.0f));
                const int j = c * 8 + 2 * p + half;
                const ulonglong2* wp = (const ulonglong2*)&cw[C_GW2 + j * 32];
#pragma unroll
                for (int q = 0; q < 8; q++) {
                    ulonglong2 w = wp[q];
                    A2[2*q]   = ffma2(had, w.x, A2[2*q]);
                    B2[2*q]   = ffma2(hbd, w.x, B2[2*q]);
                    C2[2*q]   = ffma2(hcd, w.x, C2[2*q]);
                    A2[2*q+1] = ffma2(had, w.y, A2[2*q+1]);
                    B2[2*q+1] = ffma2(hbd, w.y, B2[2*q+1]);
                    C2[2*q+1] = ffma2(hcd, w.y, C2[2*q+1]);
                }
            }
        }
    }

    // layer 3: relu(h2) -> 4 logits per sample (GW3/gb3 from smem)
    u64 lgA0, lgA1, lgB0, lgB1, lgC0, lgC1;
    {
        ulonglong2 bv = *(const ulonglong2*)&s[S_GB3];
        lgA0 = bv.x; lgA1 = bv.y;
        lgB0 = bv.x; lgB1 = bv.y;
        lgC0 = bv.x; lgC1 = bv.y;
    }
#pragma unroll
    for (int p = 0; p < 16; p++) {
        float a0, a1, b0f, b1f, c0f, c1f;
        upk2(A2[p], a0, a1);
        upk2(B2[p], b0f, b1f);
        upk2(C2[p], c0f, c1f);
#pragma unroll
        for (int half = 0; half < 2; half++) {
            const u64 had = dup2(fmaxf(half ? a1 : a0, 0.0f));
            const u64 hbd = dup2(fmaxf(half ? b1f : b0f, 0.0f));
            const u64 hcd = dup2(fmaxf(half ? c1f : c0f, 0.0f));
            const int k = 2 * p + half;
            ulonglong2 w = *(const ulonglong2*)&s[S_GW3 + k * 4];
            lgA0 = ffma2(had, w.x, lgA0);
            lgB0 = ffma2(hbd, w.x, lgB0);
            lgC0 = ffma2(hcd, w.x, lgC0);
            lgA1 = ffma2(had, w.y, lgA1);
            lgB1 = ffma2(hbd, w.y, lgB1);
            lgC1 = ffma2(hcd, w.y, lgC1);
        }
    }

    // argmax (first-max-wins) + selected expert + stores, per sample
    {
        float l0, l1, l2, l3;
        upk2(lgA0, l0, l1); upk2(lgA1, l2, l3);
        int sel = 0; float m = l0;
        if (l1 > m) { m = l1; sel = 1; }
        if (l2 > m) { m = l2; sel = 2; }
        if (l3 > m) { m = l3; sel = 3; }
        u64 o0, o1, o2;
        expert_eval(s, xa, sel, o0, o1, o2);
        u64* pp = (u64*)(pred + (size_t)b0 * OO);
        pp[0] = o0; pp[1] = o1; pp[2] = o2;
        ((ulonglong2*)(glog + (size_t)b0 * EE))[0] = make_ulonglong2(lgA0, lgA1);
    }
    {
        float l0, l1, l2, l3;
        upk2(lgB0, l0, l1); upk2(lgB1, l2, l3);
        int sel = 0; float m = l0;
        if (l1 > m) { m = l1; sel = 1; }
        if (l2 > m) { m = l2; sel = 2; }
        if (l3 > m) { m = l3; sel = 3; }
        u64 o0, o1, o2;
        expert_eval(s, xb, sel, o0, o1, o2);
        u64* pp = (u64*)(pred + (size_t)b1 * OO);
        pp[0] = o0; pp[1] = o1; pp[2] = o2;
        ((ulonglong2*)(glog + (size_t)b1 * EE))[0] = make_ulonglong2(lgB0, lgB1);
    }
    if (v2) {
        float l0, l1, l2, l3;
        upk2(lgC0, l0, l1); upk2(lgC1, l2, l3);
        int sel = 0; float m = l0;
        if (l1 > m) { m = l1; sel = 1; }
        if (l2 > m) { m = l2; sel = 2; }
        if (l3 > m) { m = l3; sel = 3; }
        u64 o0, o1, o2;
        expert_eval(s, xc, sel, o0, o1, o2);
        u64* pp = (u64*)(pred + (size_t)b2 * OO);
        pp[0] = o0; pp[1] = o1; pp[2] = o2;
        ((ulonglong2*)(glog + (size_t)b2 * EE))[0] = make_ulonglong2(lgC0, lgC1);
    }
}

extern "C" void kernel_launch(void* const* d_in, const int* in_sizes, int n_in,
                              void* d_out, int out_size) {
    const float* x   = (const float*)d_in[0];
    const float* eW1 = (const float*)d_in[1];
    const float* eb1 = (const float*)d_in[2];
    const float* eW2 = (const float*)d_in[3];
    const float* eb2 = (const float*)d_in[4];
    const float* eW3 = (const float*)d_in[5];
    const float* eb3 = (const float*)d_in[6];
    const float* gW1 = (const float*)d_in[7];
    const float* gb1 = (const float*)d_in[8];
    const float* gW2 = (const float*)d_in[9];
    const float* gb2 = (const float*)d_in[10];
    const float* gW3 = (const float*)d_in[11];
    const float* gb3 = (const float*)d_in[12];

    // two const staging nodes only
    cudaMemcpyToSymbolAsync(cw, gW1, 1088 * 4, C_GW1 * 4, cudaMemcpyDeviceToDevice);
    cudaMemcpyToSymbolAsync(cw, gW2, 2048 * 4, C_GW2 * 4, cudaMemcpyDeviceToDevice);

    const int B = in_sizes[0] / DD;
    float* out  = (float*)d_out;
    float* pred = out;                   // [B, 6]
    float* glog = out + (size_t)B * OO;  // [B, 4]

    const int Bt   = (B + 2) / 3;        // samples per partition (3 samples/thread)
    const int grid = (Bt + 127) / 128;
    moe_kernel<<<grid, 128>>>(x, eW1, eb1, eW2, eb2, eW3, eb3,
                              gb1, gb2, gW3, gb3, pred, glog, Bt, B);
}

// round 16
// speedup vs baseline: 1.0894x; 1.0894x over previous
#include <cuda_runtime.h>

typedef unsigned long long u64;

#define DD 17
#define HH 8
#define OO 6
#define EE 4

// __constant__: GW1 + GW2 (only first half of GW2 is read from const)
#define C_GW1 0            // 1088
#define C_GW2 1088         // 2048
__constant__ __align__(16) float cw[3136];

// shared: expert weights (divergent), small gating params, GW2 second-half copy
#define S_EW1 0            // 544
#define S_EB1 544          // 32
#define S_EW2 576          // 256
#define S_EB2 832          // 32
#define S_EW3 864          // 192
#define S_EB3 1056         // 24 -> pad 1088
#define S_GB1 1088         // 64
#define S_GB2 1152         // 32
#define S_GW3 1184         // 128
#define S_GB3 1312         // 4 -> pad 1328
#define S_GW2 1328         // 2048 (full copy; kernel reads only cols 16..31 per row)
#define S_TOT 3376         // 13.5 KB

__device__ __forceinline__ u64 pk2(float lo, float hi) {
    u64 r; asm("mov.b64 %0, {%1,%2};" : "=l"(r) : "f"(lo), "f"(hi)); return r;
}
__device__ __forceinline__ u64 dup2(float v) { return pk2(v, v); }
__device__ __forceinline__ void upk2(u64 v, float& lo, float& hi) {
    asm("mov.b64 {%0,%1}, %2;" : "=f"(lo), "=f"(hi) : "l"(v));
}
__device__ __forceinline__ u64 ffma2(u64 a, u64 b, u64 c) {
    u64 d; asm("fma.rn.f32x2 %0, %1, %2, %3;" : "=l"(d) : "l"(a), "l"(b), "l"(c)); return d;
}

// selected-expert MLP (smem weights, divergent by sel; x from registers)
__device__ __forceinline__ void expert_eval(const float* __restrict__ s,
                                            const float xv[DD], int sel,
                                            u64& o0, u64& o1, u64& o2)
{
    u64 e1p[4];
    {
        const ulonglong2* bp = (const ulonglong2*)&s[S_EB1 + sel * HH];
        ulonglong2 v0 = bp[0], v1 = bp[1];
        e1p[0] = v0.x; e1p[1] = v0.y; e1p[2] = v1.x; e1p[3] = v1.y;
    }
#pragma unroll
    for (int i = 0; i < DD; i++) {
        const u64 xi2 = dup2(xv[i]);
        const ulonglong2* wp = (const ulonglong2*)&s[S_EW1 + (sel * DD + i) * HH];
        ulonglong2 w0 = wp[0], w1 = wp[1];
        e1p[0] = ffma2(xi2, w0.x, e1p[0]);
        e1p[1] = ffma2(xi2, w0.y, e1p[1]);
        e1p[2] = ffma2(xi2, w1.x, e1p[2]);
        e1p[3] = ffma2(xi2, w1.y, e1p[3]);
    }
    float e1[HH];
    upk2(e1p[0], e1[0], e1[1]); upk2(e1p[1], e1[2], e1[3]);
    upk2(e1p[2], e1[4], e1[5]); upk2(e1p[3], e1[6], e1[7]);
#pragma unroll
    for (int h = 0; h < HH; h++) e1[h] = fmaxf(e1[h], 0.0f);

    u64 e2p[4];
    {
        const ulonglong2* bp = (const ulonglong2*)&s[S_EB2 + sel * HH];
        ulonglong2 v0 = bp[0], v1 = bp[1];
        e2p[0] = v0.x; e2p[1] = v0.y; e2p[2] = v1.x; e2p[3] = v1.y;
    }
#pragma unroll
    for (int h = 0; h < HH; h++) {
        const u64 hd = dup2(e1[h]);
        const ulonglong2* wp = (const ulonglong2*)&s[S_EW2 + (sel * HH + h) * HH];
        ulonglong2 w0 = wp[0], w1 = wp[1];
        e2p[0] = ffma2(hd, w0.x, e2p[0]);
        e2p[1] = ffma2(hd, w0.y, e2p[1]);
        e2p[2] = ffma2(hd, w1.x, e2p[2]);
        e2p[3] = ffma2(hd, w1.y, e2p[3]);
    }
    float e2[HH];
    upk2(e2p[0], e2[0], e2[1]); upk2(e2p[1], e2[2], e2[3]);
    upk2(e2p[2], e2[4], e2[5]); upk2(e2p[3], e2[6], e2[7]);
#pragma unroll
    for (int k = 0; k < HH; k++) e2[k] = fmaxf(e2[k], 0.0f);

    {
        const u64* bp = (const u64*)&s[S_EB3 + sel * OO];
        o0 = bp[0]; o1 = bp[1]; o2 = bp[2];
    }
#pragma unroll
    for (int k = 0; k < HH; k++) {
        const u64 kd = dup2(e2[k]);
        const u64* wp = (const u64*)&s[S_EW3 + (sel * HH + k) * OO];
        o0 = ffma2(kd, wp[0], o0);
        o1 = ffma2(kd, wp[1], o1);
        o2 = ffma2(kd, wp[2], o2);
    }
}

__global__ __launch_bounds__(128, 3) void moe_kernel(
    const float* __restrict__ x,
    const float* __restrict__ eW1, const float* __restrict__ eb1,
    const float* __restrict__ eW2, const float* __restrict__ eb2,
    const float* __restrict__ eW3, const float* __restrict__ eb3,
    const float* __restrict__ gb1, const float* __restrict__ gb2,
    const float* __restrict__ gW3, const float* __restrict__ gb3,
    const float* __restrict__ gW2,
    float* __restrict__ pred, float* __restrict__ glog, int Bhalf)
{
    __shared__ __align__(16) float s[S_TOT];
    const int t = threadIdx.x;
    // expert weights -> smem
    for (int i = t; i < 544; i += 128) s[S_EW1 + i] = eW1[i];
    if (t < 32)  s[S_EB1 + t] = eb1[t];
    for (int i = t; i < 256; i += 128) s[S_EW2 + i] = eW2[i];
    if (t >= 32 && t < 64) s[S_EB2 + (t - 32)] = eb2[t - 32];
    for (int i = t; i < 192; i += 128) s[S_EW3 + i] = eW3[i];
    if (t >= 64 && t < 88) s[S_EB3 + (t - 64)] = eb3[t - 64];
    // small gating params -> smem
    if (t < 64)  s[S_GB1 + t] = gb1[t];
    if (t >= 64 && t < 96) s[S_GB2 + (t - 64)] = gb2[t - 64];
    s[S_GW3 + t] = gW3[t];
    if (t >= 96 && t < 100) s[S_GB3 + (t - 96)] = gb3[t - 96];
    // GW2 -> smem (second half of each row is read from here; port split)
    for (int i = t; i < 2048; i += 128) s[S_GW2 + i] = gW2[i];
    __syncthreads();

    const int ba = blockIdx.x * 128 + t;   // first sample
    const int bb = ba + Bhalf;             // second sample (coalesced pairing)

    // x rows: direct per-thread global loads into registers (once)
    float xa[DD], xb[DD];
    {
        const float* ra = x + (size_t)ba * DD;
        const float* rb = x + (size_t)bb * DD;
#pragma unroll
        for (int i = 0; i < DD; i++) { xa[i] = ra[i]; xb[i] = rb[i]; }
    }

    // gating layer-2 accumulators (bias from smem broadcast)
    u64 A2[16], B2[16];
    {
        const ulonglong2* bp = (const ulonglong2*)&s[S_GB2];
#pragma unroll
        for (int q = 0; q < 8; q++) {
            ulonglong2 v = bp[q];
            A2[2*q]   = v.x; B2[2*q]   = v.x;
            A2[2*q+1] = v.y; B2[2*q+1] = v.y;
        }
    }

    // layer1 in 16-neuron chunks (GW1 const), fused into layer2
    // layer2 weight rows split: cols 0..15 from const (LDC port), cols 16..31 from smem (LSU port)
#pragma unroll
    for (int c = 0; c < 4; c++) {
        u64 A1[8], B1[8];
        {
            const ulonglong2* bp = (const ulonglong2*)&s[S_GB1 + c * 16];
#pragma unroll
            for (int q = 0; q < 4; q++) {
                ulonglong2 v = bp[q];
                A1[2*q] = v.x; A1[2*q+1] = v.y;
                B1[2*q] = v.x; B1[2*q+1] = v.y;
            }
        }
#pragma unroll
        for (int i = 0; i < DD; i++) {
            const u64 xad = dup2(xa[i]);
            const u64 xbd = dup2(xb[i]);
            const ulonglong2* wp = (const ulonglong2*)&cw[C_GW1 + i * 64 + c * 16];
#pragma unroll
            for (int q = 0; q < 4; q++) {
                ulonglong2 w = wp[q];
                A1[2*q]   = ffma2(xad, w.x, A1[2*q]);
                B1[2*q]   = ffma2(xbd, w.x, B1[2*q]);
                A1[2*q+1] = ffma2(xad, w.y, A1[2*q+1]);
                B1[2*q+1] = ffma2(xbd, w.y, B1[2*q+1]);
            }
        }
        // relu + feed into layer 2
#pragma unroll
        for (int p = 0; p < 8; p++) {
            float a0, a1, b0, b1;
            upk2(A1[p], a0, a1);
            upk2(B1[p], b0, b1);
#pragma unroll
            for (int half = 0; half < 2; half++) {
                const u64 had = dup2(fmaxf(half ? a1 : a0, 0.0f));
                const u64 hbd = dup2(fmaxf(half ? b1 : b0, 0.0f));
                const int j = c * 16 + 2 * p + half;
                const ulonglong2* wpC = (const ulonglong2*)&cw[C_GW2 + j * 32];
                const ulonglong2* wpS = (const ulonglong2*)&s[S_GW2 + j * 32];
#pragma unroll
                for (int q = 0; q < 8; q++) {
                    ulonglong2 w = (q < 4) ? wpC[q] : wpS[q];   // port split
                    A2[2*q]   = ffma2(had, w.x, A2[2*q]);
                    B2[2*q]   = ffma2(hbd, w.x, B2[2*q]);
                    A2[2*q+1] = ffma2(had, w.y, A2[2*q+1]);
                    B2[2*q+1] = ffma2(hbd, w.y, B2[2*q+1]);
                }
            }
        }
    }

    // layer 3: relu(h2) -> 4 logits (GW3/gb3 from smem)
    u64 lgA0, lgA1, lgB0, lgB1;
    {
        ulonglong2 bv = *(const ulonglong2*)&s[S_GB3];
        lgA0 = bv.x; lgA1 = bv.y;
        lgB0 = bv.x; lgB1 = bv.y;
    }
#pragma unroll
    for (int p = 0; p < 16; p++) {
        float a0, a1, b0, b1;
        upk2(A2[p], a0, a1);
        upk2(B2[p], b0, b1);
#pragma unroll
        for (int half = 0; half < 2; half++) {
            const u64 had = dup2(fmaxf(half ? a1 : a0, 0.0f));
            const u64 hbd = dup2(fmaxf(half ? b1 : b0, 0.0f));
            const int k = 2 * p + half;
            ulonglong2 w = *(const ulonglong2*)&s[S_GW3 + k * 4];
            lgA0 = ffma2(had, w.x, lgA0);
            lgB0 = ffma2(hbd, w.x, lgB0);
            lgA1 = ffma2(had, w.y, lgA1);
            lgB1 = ffma2(hbd, w.y, lgB1);
        }
    }

    // argmax (first-max-wins, matches jnp.argmax)
    float la0, la1, la2, la3, lb0, lb1, lb2, lb3;
    upk2(lgA0, la0, la1); upk2(lgA1, la2, la3);
    upk2(lgB0, lb0, lb1); upk2(lgB1, lb2, lb3);
    int selA = 0; float mA = la0;
    if (la1 > mA) { mA = la1; selA = 1; }
    if (la2 > mA) { mA = la2; selA = 2; }
    if (la3 > mA) { mA = la3; selA = 3; }
    int selB = 0; float mB = lb0;
    if (lb1 > mB) { mB = lb1; selB = 1; }
    if (lb2 > mB) { mB = lb2; selB = 2; }
    if (lb3 > mB) { mB = lb3; selB = 3; }

    u64 oA0, oA1, oA2, oB0, oB1, oB2;
    expert_eval(s, xa, selA, oA0, oA1, oA2);
    expert_eval(s, xb, selB, oB0, oB1, oB2);

    {
        u64* p0 = (u64*)(pred + (size_t)ba * OO);
        p0[0] = oA0; p0[1] = oA1; p0[2] = oA2;
        u64* p1 = (u64*)(pred + (size_t)bb * OO);
        p1[0] = oB0; p1[1] = oB1; p1[2] = oB2;
        ulonglong2* l0 = (ulonglong2*)(glog + (size_t)ba * EE);
        l0[0] = make_ulonglong2(lgA0, lgA1);
        ulonglong2* l1 = (ulonglong2*)(glog + (size_t)bb * EE);
        l1[0] = make_ulonglong2(lgB0, lgB1);
    }
}

extern "C" void kernel_launch(void* const* d_in, const int* in_sizes, int n_in,
                              void* d_out, int out_size) {
    const float* x   = (const float*)d_in[0];
    const float* eW1 = (const float*)d_in[1];
    const float* eb1 = (const float*)d_in[2];
    const float* eW2 = (const float*)d_in[3];
    const float* eb2 = (const float*)d_in[4];
    const float* eW3 = (const float*)d_in[5];
    const float* eb3 = (const float*)d_in[6];
    const float* gW1 = (const float*)d_in[7];
    const float* gb1 = (const float*)d_in[8];
    const float* gW2 = (const float*)d_in[9];
    const float* gb2 = (const float*)d_in[10];
    const float* gW3 = (const float*)d_in[11];
    const float* gb3 = (const float*)d_in[12];

    // two const staging nodes only
    cudaMemcpyToSymbolAsync(cw, gW1, 1088 * 4, C_GW1 * 4, cudaMemcpyDeviceToDevice);
    cudaMemcpyToSymbolAsync(cw, gW2, 2048 * 4, C_GW2 * 4, cudaMemcpyDeviceToDevice);

    const int B = in_sizes[0] / DD;
    float* out  = (float*)d_out;
    float* pred = out;                   // [B, 6]
    float* glog = out + (size_t)B * OO;  // [B, 4]

    const int grid = B / 256;            // 128 threads/block, 2 samples/thread
    moe_kernel<<<grid, 128>>>(x, eW1, eb1, eW2, eb2, eW3, eb3,
                              gb1, gb2, gW3, gb3, gW2, pred, glog, B / 2);
}

// round 17
// speedup vs baseline: 1.1478x; 1.0536x over previous
#include <cuda_runtime.h>

typedef unsigned long long u64;

#define DD 17
#define HH 8
#define OO 6
#define EE 4

// __constant__: GW1 + GW2 only (2 memcpy graph nodes)
#define C_GW1 0            // 1088
#define C_GW2 1088         // 2048
__constant__ __align__(16) float cw[3136];

// shared: expert weights (divergent) + small gating params
#define S_EW1 0            // 544
#define S_EB1 544          // 32
#define S_EW2 576          // 256
#define S_EB2 832          // 32
#define S_EW3 864          // 192
#define S_EB3 1056         // 24 -> pad 1088
#define S_GB1 1088         // 64
#define S_GB2 1152         // 32
#define S_GW3 1184         // 128
#define S_GB3 1312         // 4 -> pad 1328
#define S_TOT 1328

__device__ __forceinline__ u64 pk2(float lo, float hi) {
    u64 r; asm("mov.b64 %0, {%1,%2};" : "=l"(r) : "f"(lo), "f"(hi)); return r;
}
__device__ __forceinline__ u64 dup2(float v) { return pk2(v, v); }
__device__ __forceinline__ void upk2(u64 v, float& lo, float& hi) {
    asm("mov.b64 {%0,%1}, %2;" : "=f"(lo), "=f"(hi) : "l"(v));
}
__device__ __forceinline__ u64 ffma2(u64 a, u64 b, u64 c) {
    u64 d; asm("fma.rn.f32x2 %0, %1, %2, %3;" : "=l"(d) : "l"(a), "l"(b), "l"(c)); return d;
}

// dual selected-expert MLP: both samples interleaved -> 8 independent chains
// (per-accumulator arithmetic order identical to the single-sample version)
__device__ __forceinline__ void expert_eval_dual(
    const float* __restrict__ s,
    const float xva[DD], int selA,
    const float xvb[DD], int selB,
    u64& oA0, u64& oA1, u64& oA2,
    u64& oB0, u64& oB1, u64& oB2)
{
    u64 eA[4], eB[4];
    {
        const ulonglong2* ba = (const ulonglong2*)&s[S_EB1 + selA * HH];
        const ulonglong2* bb = (const ulonglong2*)&s[S_EB1 + selB * HH];
        ulonglong2 a0 = ba[0], a1 = ba[1], b0 = bb[0], b1 = bb[1];
        eA[0] = a0.x; eA[1] = a0.y; eA[2] = a1.x; eA[3] = a1.y;
        eB[0] = b0.x; eB[1] = b0.y; eB[2] = b1.x; eB[3] = b1.y;
    }
#pragma unroll
    for (int i = 0; i < DD; i++) {
        const u64 xiA = dup2(xva[i]);
        const u64 xiB = dup2(xvb[i]);
        const ulonglong2* wpa = (const ulonglong2*)&s[S_EW1 + (selA * DD + i) * HH];
        const ulonglong2* wpb = (const ulonglong2*)&s[S_EW1 + (selB * DD + i) * HH];
        ulonglong2 wa0 = wpa[0], wb0 = wpb[0];
        eA[0] = ffma2(xiA, wa0.x, eA[0]);
        eB[0] = ffma2(xiB, wb0.x, eB[0]);
        eA[1] = ffma2(xiA, wa0.y, eA[1]);
        eB[1] = ffma2(xiB, wb0.y, eB[1]);
        ulonglong2 wa1 = wpa[1], wb1 = wpb[1];
        eA[2] = ffma2(xiA, wa1.x, eA[2]);
        eB[2] = ffma2(xiB, wb1.x, eB[2]);
        eA[3] = ffma2(xiA, wa1.y, eA[3]);
        eB[3] = ffma2(xiB, wb1.y, eB[3]);
    }
    float e1A[HH], e1B[HH];
    upk2(eA[0], e1A[0], e1A[1]); upk2(eA[1], e1A[2], e1A[3]);
    upk2(eA[2], e1A[4], e1A[5]); upk2(eA[3], e1A[6], e1A[7]);
    upk2(eB[0], e1B[0], e1B[1]); upk2(eB[1], e1B[2], e1B[3]);
    upk2(eB[2], e1B[4], e1B[5]); upk2(eB[3], e1B[6], e1B[7]);
#pragma unroll
    for (int h = 0; h < HH; h++) { e1A[h] = fmaxf(e1A[h], 0.0f); e1B[h] = fmaxf(e1B[h], 0.0f); }

    u64 fA[4], fB[4];
    {
        const ulonglong2* ba = (const ulonglong2*)&s[S_EB2 + selA * HH];
        const ulonglong2* bb = (const ulonglong2*)&s[S_EB2 + selB * HH];
        ulonglong2 a0 = ba[0], a1 = ba[1], b0 = bb[0], b1 = bb[1];
        fA[0] = a0.x; fA[1] = a0.y; fA[2] = a1.x; fA[3] = a1.y;
        fB[0] = b0.x; fB[1] = b0.y; fB[2] = b1.x; fB[3] = b1.y;
    }
#pragma unroll
    for (int h = 0; h < HH; h++) {
        const u64 hA = dup2(e1A[h]);
        const u64 hB = dup2(e1B[h]);
        const ulonglong2* wpa = (const ulonglong2*)&s[S_EW2 + (selA * HH + h) * HH];
        const ulonglong2* wpb = (const ulonglong2*)&s[S_EW2 + (selB * HH + h) * HH];
        ulonglong2 wa0 = wpa[0], wb0 = wpb[0];
        fA[0] = ffma2(hA, wa0.x, fA[0]);
        fB[0] = ffma2(hB, wb0.x, fB[0]);
        fA[1] = ffma2(hA, wa0.y, fA[1]);
        fB[1] = ffma2(hB, wb0.y, fB[1]);
        ulonglong2 wa1 = wpa[1], wb1 = wpb[1];
        fA[2] = ffma2(hA, wa1.x, fA[2]);
        fB[2] = ffma2(hB, wb1.x, fB[2]);
        fA[3] = ffma2(hA, wa1.y, fA[3]);
        fB[3] = ffma2(hB, wb1.y, fB[3]);
    }
    float e2A[HH], e2B[HH];
    upk2(fA[0], e2A[0], e2A[1]); upk2(fA[1], e2A[2], e2A[3]);
    upk2(fA[2], e2A[4], e2A[5]); upk2(fA[3], e2A[6], e2A[7]);
    upk2(fB[0], e2B[0], e2B[1]); upk2(fB[1], e2B[2], e2B[3]);
    upk2(fB[2], e2B[4], e2B[5]); upk2(fB[3], e2B[6], e2B[7]);
#pragma unroll
    for (int k = 0; k < HH; k++) { e2A[k] = fmaxf(e2A[k], 0.0f); e2B[k] = fmaxf(e2B[k], 0.0f); }

    {
        const u64* ba = (const u64*)&s[S_EB3 + selA * OO];
        const u64* bb = (const u64*)&s[S_EB3 + selB * OO];
        oA0 = ba[0]; oA1 = ba[1]; oA2 = ba[2];
        oB0 = bb[0]; oB1 = bb[1]; oB2 = bb[2];
    }
#pragma unroll
    for (int k = 0; k < HH; k++) {
        const u64 kA = dup2(e2A[k]);
        const u64 kB = dup2(e2B[k]);
        const u64* wpa = (const u64*)&s[S_EW3 + (selA * HH + k) * OO];
        const u64* wpb = (const u64*)&s[S_EW3 + (selB * HH + k) * OO];
        oA0 = ffma2(kA, wpa[0], oA0);
        oB0 = ffma2(kB, wpb[0], oB0);
        oA1 = ffma2(kA, wpa[1], oA1);
        oB1 = ffma2(kB, wpb[1], oB1);
        oA2 = ffma2(kA, wpa[2], oA2);
        oB2 = ffma2(kB, wpb[2], oB2);
    }
}

__global__ __launch_bounds__(128, 3) void moe_kernel(
    const float* __restrict__ x,
    const float* __restrict__ eW1, const float* __restrict__ eb1,
    const float* __restrict__ eW2, const float* __restrict__ eb2,
    const float* __restrict__ eW3, const float* __restrict__ eb3,
    const float* __restrict__ gb1, const float* __restrict__ gb2,
    const float* __restrict__ gW3, const float* __restrict__ gb3,
    float* __restrict__ pred, float* __restrict__ glog, int Bhalf)
{
    __shared__ __align__(16) float s[S_TOT];
    const int t = threadIdx.x;
    // expert weights -> smem
    for (int i = t; i < 544; i += 128) s[S_EW1 + i] = eW1[i];
    if (t < 32)  s[S_EB1 + t] = eb1[t];
    for (int i = t; i < 256; i += 128) s[S_EW2 + i] = eW2[i];
    if (t >= 32 && t < 64) s[S_EB2 + (t - 32)] = eb2[t - 32];
    for (int i = t; i < 192; i += 128) s[S_EW3 + i] = eW3[i];
    if (t >= 64 && t < 88) s[S_EB3 + (t - 64)] = eb3[t - 64];
    // small gating params -> smem
    if (t < 64)  s[S_GB1 + t] = gb1[t];
    if (t >= 64 && t < 96) s[S_GB2 + (t - 64)] = gb2[t - 64];
    s[S_GW3 + t] = gW3[t];
    if (t >= 96 && t < 100) s[S_GB3 + (t - 96)] = gb3[t - 96];
    __syncthreads();

    const int ba = blockIdx.x * 128 + t;   // first sample
    const int bb = ba + Bhalf;             // second sample (coalesced pairing)

    // x rows: direct per-thread global loads into registers (once)
    float xa[DD], xb[DD];
    {
        const float* ra = x + (size_t)ba * DD;
        const float* rb = x + (size_t)bb * DD;
#pragma unroll
        for (int i = 0; i < DD; i++) { xa[i] = ra[i]; xb[i] = rb[i]; }
    }

    // gating layer-2 accumulators (bias from smem broadcast)
    u64 A2[16], B2[16];
    {
        const ulonglong2* bp = (const ulonglong2*)&s[S_GB2];
#pragma unroll
        for (int q = 0; q < 8; q++) {
            ulonglong2 v = bp[q];
            A2[2*q]   = v.x; B2[2*q]   = v.x;
            A2[2*q+1] = v.y; B2[2*q+1] = v.y;
        }
    }

    // layer1 in 16-neuron chunks (GW1 const), fused into layer2 (GW2 const)
#pragma unroll
    for (int c = 0; c < 4; c++) {
        u64 A1[8], B1[8];
        {
            const ulonglong2* bp = (const ulonglong2*)&s[S_GB1 + c * 16];
#pragma unroll
            for (int q = 0; q < 4; q++) {
                ulonglong2 v = bp[q];
                A1[2*q] = v.x; A1[2*q+1] = v.y;
                B1[2*q] = v.x; B1[2*q+1] = v.y;
            }
        }
#pragma unroll
        for (int i = 0; i < DD; i++) {
            const u64 xad = dup2(xa[i]);
            const u64 xbd = dup2(xb[i]);
            const ulonglong2* wp = (const ulonglong2*)&cw[C_GW1 + i * 64 + c * 16];
#pragma unroll
            for (int q = 0; q < 4; q++) {
                ulonglong2 w = wp[q];
                A1[2*q]   = ffma2(xad, w.x, A1[2*q]);
                B1[2*q]   = ffma2(xbd, w.x, B1[2*q]);
                A1[2*q+1] = ffma2(xad, w.y, A1[2*q+1]);
                B1[2*q+1] = ffma2(xbd, w.y, B1[2*q+1]);
            }
        }
        // relu + feed into layer 2 (GW2 const rows of 32)
#pragma unroll
        for (int p = 0; p < 8; p++) {
            float a0, a1, b0, b1;
            upk2(A1[p], a0, a1);
            upk2(B1[p], b0, b1);
#pragma unroll
            for (int half = 0; half < 2; half++) {
                const u64 had = dup2(fmaxf(half ? a1 : a0, 0.0f));
                const u64 hbd = dup2(fmaxf(half ? b1 : b0, 0.0f));
                const int j = c * 16 + 2 * p + half;
                const ulonglong2* wp = (const ulonglong2*)&cw[C_GW2 + j * 32];
#pragma unroll
                for (int q = 0; q < 8; q++) {
                    ulonglong2 w = wp[q];
                    A2[2*q]   = ffma2(had, w.x, A2[2*q]);
                    B2[2*q]   = ffma2(hbd, w.x, B2[2*q]);
                    A2[2*q+1] = ffma2(had, w.y, A2[2*q+1]);
                    B2[2*q+1] = ffma2(hbd, w.y, B2[2*q+1]);
                }
            }
        }
    }

    // layer 3: relu(h2) -> 4 logits (GW3/gb3 from smem)
    u64 lgA0, lgA1, lgB0, lgB1;
    {
        ulonglong2 bv = *(const ulonglong2*)&s[S_GB3];
        lgA0 = bv.x; lgA1 = bv.y;
        lgB0 = bv.x; lgB1 = bv.y;
    }
#pragma unroll
    for (int p = 0; p < 16; p++) {
        float a0, a1, b0, b1;
        upk2(A2[p], a0, a1);
        upk2(B2[p], b0, b1);
#pragma unroll
        for (int half = 0; half < 2; half++) {
            const u64 had = dup2(fmaxf(half ? a1 : a0, 0.0f));
            const u64 hbd = dup2(fmaxf(half ? b1 : b0, 0.0f));
            const int k = 2 * p + half;
            ulonglong2 w = *(const ulonglong2*)&s[S_GW3 + k * 4];
            lgA0 = ffma2(had, w.x, lgA0);
            lgB0 = ffma2(hbd, w.x, lgB0);
            lgA1 = ffma2(had, w.y, lgA1);
            lgB1 = ffma2(hbd, w.y, lgB1);
        }
    }

    // argmax (first-max-wins, matches jnp.argmax)
    float la0, la1, la2, la3, lb0, lb1, lb2, lb3;
    upk2(lgA0, la0, la1); upk2(lgA1, la2, la3);
    upk2(lgB0, lb0, lb1); upk2(lgB1, lb2, lb3);
    int selA = 0; float mA = la0;
    if (la1 > mA) { mA = la1; selA = 1; }
    if (la2 > mA) { mA = la2; selA = 2; }
    if (la3 > mA) { mA = la3; selA = 3; }
    int selB = 0; float mB = lb0;
    if (lb1 > mB) { mB = lb1; selB = 1; }
    if (lb2 > mB) { mB = lb2; selB = 2; }
    if (lb3 > mB) { mB = lb3; selB = 3; }

    // interleaved dual expert evaluation (8 independent chains)
    u64 oA0, oA1, oA2, oB0, oB1, oB2;
    expert_eval_dual(s, xa, selA, xb, selB, oA0, oA1, oA2, oB0, oB1, oB2);

    {
        u64* p0 = (u64*)(pred + (size_t)ba * OO);
        p0[0] = oA0; p0[1] = oA1; p0[2] = oA2;
        u64* p1 = (u64*)(pred + (size_t)bb * OO);
        p1[0] = oB0; p1[1] = oB1; p1[2] = oB2;
        ulonglong2* l0 = (ulonglong2*)(glog + (size_t)ba * EE);
        l0[0] = make_ulonglong2(lgA0, lgA1);
        ulonglong2* l1 = (ulonglong2*)(glog + (size_t)bb * EE);
        l1[0] = make_ulonglong2(lgB0, lgB1);
    }
}

extern "C" void kernel_launch(void* const* d_in, const int* in_sizes, int n_in,
                              void* d_out, int out_size) {
    const float* x   = (const float*)d_in[0];
    const float* eW1 = (const float*)d_in[1];
    const float* eb1 = (const float*)d_in[2];
    const float* eW2 = (const float*)d_in[3];
    const float* eb2 = (const float*)d_in[4];
    const float* eW3 = (const float*)d_in[5];
    const float* eb3 = (const float*)d_in[6];
    const float* gW1 = (const float*)d_in[7];
    const float* gb1 = (const float*)d_in[8];
    const float* gW2 = (const float*)d_in[9];
    const float* gb2 = (const float*)d_in[10];
    const float* gW3 = (const float*)d_in[11];
    const float* gb3 = (const float*)d_in[12];

    // two const staging nodes only
    cudaMemcpyToSymbolAsync(cw, gW1, 1088 * 4, C_GW1 * 4, cudaMemcpyDeviceToDevice);
    cudaMemcpyToSymbolAsync(cw, gW2, 2048 * 4, C_GW2 * 4, cudaMemcpyDeviceToDevice);

    const int B = in_sizes[0] / DD;
    float* out  = (float*)d_out;
    float* pred = out;                   // [B, 6]
    float* glog = out + (size_t)B * OO;  // [B, 4]

    const int grid = B / 256;            // 128 threads/block, 2 samples/thread
    moe_kernel<<<grid, 128>>>(x, eW1, eb1, eW2, eb2, eW3, eb3,
                              gb1, gb2, gW3, gb3, pred, glog, B / 2);
}